// round 7
// baseline (speedup 1.0000x reference)
#include <cuda_runtime.h>

#define NB 8192
#define NP 4849
#define PPAD 4864      // padded row stride (multiple of 16 floats -> float4-aligned rows)
#define NH 96
#define NW 48
#define NSTEPS 20

// Scratch (device globals: allocation-free per the harness rules)
__device__ float g_h[NB * NH];                      // 3.1 MB   hyper hidden
__device__ float g_params[(size_t)NB * PPAD];       // 159 MB   per-sample flat params

__device__ __forceinline__ float sigmoidf(float z) {
    return 1.0f / (1.0f + __expf(-z));
}

// ---------------------------------------------------------------------------
// Kernel 0: h[b,k] = relu(hw1[k,0]*x[b] + hw1[k,1]*c[b] + hb1[k])
// ---------------------------------------------------------------------------
__global__ void hyper_h_kernel(const float* __restrict__ x, const float* __restrict__ c,
                               const float* __restrict__ hw1, const float* __restrict__ hb1) {
    int idx = blockIdx.x * blockDim.x + threadIdx.x;
    if (idx >= NB * NH) return;
    int b = idx / NH;
    int k = idx - b * NH;
    float v = fmaf(hw1[2 * k], x[b], fmaf(hw1[2 * k + 1], c[b], hb1[k]));
    g_h[idx] = fmaxf(v, 0.0f);
}

// ---------------------------------------------------------------------------
// Kernel 1: g_params[b, j] = hb2[j] + sum_k g_h[b,k] * hw2[j,k]
// M=8192, N=4849 (padded 4864), K=96.  128x128 tile, 8x8 per thread, BK=32.
// ---------------------------------------------------------------------------
#define BM 128
#define BN 128
#define BK 32
#define LDT (BM + 4)   // 132: row starts stay 16B-aligned; odd-ish bank pattern

__global__ __launch_bounds__(256, 2) void hyper_gemm_kernel(const float* __restrict__ hw2,
                                                            const float* __restrict__ hb2) {
    __shared__ __align__(16) float As[BK][LDT];
    __shared__ __align__(16) float Bs[BK][LDT];

    const int b0 = blockIdx.x * BM;
    const int j0 = blockIdx.y * BN;
    const int tid = threadIdx.x;
    const int tr = tid >> 4;    // 0..15 -> output rows tr*8..tr*8+7
    const int tc = tid & 15;    // 0..15 -> output cols tc*8..tc*8+7

    float acc[8][8];
#pragma unroll
    for (int i = 0; i < 8; i++)
#pragma unroll
        for (int j = 0; j < 8; j++) acc[i][j] = 0.0f;

    for (int k0 = 0; k0 < NH; k0 += BK) {
        // Load A tile: As[kk][m] = g_h[(b0+m)*96 + k0+kk]   (coalesced over kk)
#pragma unroll
        for (int l = 0; l < (BM * BK) / 256; l++) {
            int idx = tid + l * 256;
            int m = idx >> 5;        // / BK
            int kk = idx & 31;       // % BK
            As[kk][m] = g_h[(b0 + m) * NH + k0 + kk];
        }
        // Load B tile: Bs[kk][j] = hw2[(j0+j)*96 + k0+kk]   (coalesced over kk)
#pragma unroll
        for (int l = 0; l < (BN * BK) / 256; l++) {
            int idx = tid + l * 256;
            int j = idx >> 5;
            int kk = idx & 31;
            int jj = j0 + j;
            Bs[kk][j] = (jj < NP) ? hw2[jj * NH + k0 + kk] : 0.0f;
        }
        __syncthreads();

#pragma unroll
        for (int kk = 0; kk < BK; kk++) {
            float4 a0 = *(const float4*)&As[kk][tr * 8];
            float4 a1 = *(const float4*)&As[kk][tr * 8 + 4];
            float4 b0v = *(const float4*)&Bs[kk][tc * 8];
            float4 b1v = *(const float4*)&Bs[kk][tc * 8 + 4];
            float av[8] = {a0.x, a0.y, a0.z, a0.w, a1.x, a1.y, a1.z, a1.w};
            float bw[8] = {b0v.x, b0v.y, b0v.z, b0v.w, b1v.x, b1v.y, b1v.z, b1v.w};
#pragma unroll
            for (int i = 0; i < 8; i++)
#pragma unroll
                for (int j = 0; j < 8; j++)
                    acc[i][j] = fmaf(av[i], bw[j], acc[i][j]);
        }
        __syncthreads();
    }

    float bias[8];
#pragma unroll
    for (int j = 0; j < 8; j++) {
        int jj = j0 + tc * 8 + j;
        bias[j] = (jj < NP) ? hb2[jj] : 0.0f;
    }
#pragma unroll
    for (int i = 0; i < 8; i++) {
        float* o = &g_params[(size_t)(b0 + tr * 8 + i) * PPAD + j0 + tc * 8];
        float4 v0 = make_float4(acc[i][0] + bias[0], acc[i][1] + bias[1],
                                acc[i][2] + bias[2], acc[i][3] + bias[3]);
        float4 v1 = make_float4(acc[i][4] + bias[4], acc[i][5] + bias[5],
                                acc[i][6] + bias[6], acc[i][7] + bias[7]);
        *(float4*)o = v0;
        *(float4*)(o + 4) = v1;
    }
}

// ---------------------------------------------------------------------------
// Kernel 2: 20 Adam steps per sample.  g = dE/dy via forward + JVP through the
// 48-wide swish MLP.  96 threads / 2 samples per block; thread i owns row i of
// w1 and w2 in registers; activations shared via smem (broadcast reads).
// ---------------------------------------------------------------------------
__global__ __launch_bounds__(96, 4) void adam_kernel(float* __restrict__ out) {
    __shared__ __align__(16) float h0s[2][48];
    __shared__ __align__(16) float dh0s[2][48];
    __shared__ __align__(16) float h1s[2][48];
    __shared__ __align__(16) float dh1s[2][48];
    __shared__ __align__(16) float part[2][48];

    const int tid = threadIdx.x;
    const int s = tid / 48;          // sample slot within block (0 or 1)
    const int i = tid - s * 48;      // row 0..47
    const int sample = blockIdx.x * 2 + s;

    const float* p = g_params + (size_t)sample * PPAD;

    // Per-row params (layout: w0[48] b0[48] w1[48x48] b1[48] w2[48x48] b2[48] w3[48] b3)
    const float w0i = p[i];
    const float b0i = p[48 + i];
    const float b1i = p[2400 + i];
    const float b2i = p[4752 + i];
    const float w3i = p[4800 + i];

    float w1r[48], w2r[48];
    {
        const float4* p1 = (const float4*)(p + 96 + i * 48);    // offset % 4 == 0, row base 16B-aligned
        const float4* p2 = (const float4*)(p + 2448 + i * 48);
#pragma unroll
        for (int q = 0; q < 12; q++) {
            float4 a = p1[q];
            w1r[4 * q + 0] = a.x; w1r[4 * q + 1] = a.y; w1r[4 * q + 2] = a.z; w1r[4 * q + 3] = a.w;
            float4 b = p2[q];
            w2r[4 * q + 0] = b.x; w2r[4 * q + 1] = b.y; w2r[4 * q + 2] = b.z; w2r[4 * q + 3] = b.w;
        }
    }

    float y = 0.0f, mA = 0.0f, vA = 0.0f, pb1 = 1.0f, pb2 = 1.0f;

#pragma unroll 1
    for (int t = 0; t < NSTEPS; t++) {
        // Layer 0 (scalar input): z0 = w0*y + b0 ; tangent dz0 = w0
        float z0 = fmaf(w0i, y, b0i);
        float s0 = sigmoidf(z0);
        h0s[s][i]  = z0 * s0;
        dh0s[s][i] = (s0 + z0 * s0 * (1.0f - s0)) * w0i;
        __syncthreads();

        // Layer 1: z1_i = b1_i + w1[i,:]·h0 ; dz1_i = w1[i,:]·dh0
        float acc = b1i, dacc = 0.0f;
        {
            const float4* h4 = (const float4*)h0s[s];
            const float4* d4 = (const float4*)dh0s[s];
#pragma unroll
            for (int q = 0; q < 12; q++) {
                float4 hv = h4[q], dv = d4[q];
                acc  = fmaf(w1r[4 * q + 0], hv.x, acc);
                acc  = fmaf(w1r[4 * q + 1], hv.y, acc);
                acc  = fmaf(w1r[4 * q + 2], hv.z, acc);
                acc  = fmaf(w1r[4 * q + 3], hv.w, acc);
                dacc = fmaf(w1r[4 * q + 0], dv.x, dacc);
                dacc = fmaf(w1r[4 * q + 1], dv.y, dacc);
                dacc = fmaf(w1r[4 * q + 2], dv.z, dacc);
                dacc = fmaf(w1r[4 * q + 3], dv.w, dacc);
            }
        }
        float s1 = sigmoidf(acc);
        h1s[s][i]  = acc * s1;
        dh1s[s][i] = (s1 + acc * s1 * (1.0f - s1)) * dacc;
        __syncthreads();

        // Layer 2
        acc = b2i; dacc = 0.0f;
        {
            const float4* h4 = (const float4*)h1s[s];
            const float4* d4 = (const float4*)dh1s[s];
#pragma unroll
            for (int q = 0; q < 12; q++) {
                float4 hv = h4[q], dv = d4[q];
                acc  = fmaf(w2r[4 * q + 0], hv.x, acc);
                acc  = fmaf(w2r[4 * q + 1], hv.y, acc);
                acc  = fmaf(w2r[4 * q + 2], hv.z, acc);
                acc  = fmaf(w2r[4 * q + 3], hv.w, acc);
                dacc = fmaf(w2r[4 * q + 0], dv.x, dacc);
                dacc = fmaf(w2r[4 * q + 1], dv.y, dacc);
                dacc = fmaf(w2r[4 * q + 2], dv.z, dacc);
                dacc = fmaf(w2r[4 * q + 3], dv.w, dacc);
            }
        }
        float s2 = sigmoidf(acc);
        // out-layer tangent contribution: w3_i * dh2_i   (b3 drops out of the gradient)
        part[s][i] = w3i * ((s2 + acc * s2 * (1.0f - s2)) * dacc);
        __syncthreads();

        // g = sum_i part_i  (redundantly in all threads: deterministic, saves a barrier)
        float g = 0.0f;
        {
            const float4* q4 = (const float4*)part[s];
#pragma unroll
            for (int q = 0; q < 12; q++) {
                float4 pv = q4[q];
                g += ((pv.x + pv.y) + (pv.z + pv.w));
            }
        }

        // Adam update (each thread keeps an identical copy of the scalar state)
        pb1 *= 0.9f;
        pb2 *= 0.999f;
        mA = 0.9f * mA + 0.1f * g;
        vA = 0.999f * vA + 0.001f * g * g;
        float mh = mA / (1.0f - pb1);
        float vh = vA / (1.0f - pb2);
        y -= 0.1f * mh / (sqrtf(vh) + 1e-8f);
    }

    if (i == 0) out[sample] = y;
}

// ---------------------------------------------------------------------------
extern "C" void kernel_launch(void* const* d_in, const int* in_sizes, int n_in,
                              void* d_out, int out_size) {
    const float* x   = (const float*)d_in[0];   // (8192,1)
    const float* c   = (const float*)d_in[1];   // (8192,1)
    const float* hw1 = (const float*)d_in[2];   // (96,2)
    const float* hb1 = (const float*)d_in[3];   // (96,)
    const float* hw2 = (const float*)d_in[4];   // (4849,96)
    const float* hb2 = (const float*)d_in[5];   // (4849,)
    float* out = (float*)d_out;                 // (8192,1)

    (void)in_sizes; (void)n_in; (void)out_size;

    hyper_h_kernel<<<(NB * NH + 255) / 256, 256>>>(x, c, hw1, hb1);

    dim3 grid(NB / BM, (NP + BN - 1) / BN);     // (64, 38)
    hyper_gemm_kernel<<<grid, 256>>>(hw2, hb2);

    adam_kernel<<<NB / 2, 96>>>(out);
}